// round 1
// baseline (speedup 1.0000x reference)
#include <cuda_runtime.h>
#include <cuda_bf16.h>
#include <math.h>

// Problem shape (fixed by reference setup_inputs)
#define B_    2
#define N_    4096     // pred points per batch
#define M_    4096     // target points per batch (== N_)
#define L_    512      // latent dim
#define TPB   128      // threads per block in pairmin
#define KQ    4        // queries per thread (register blocking)
#define TILE  128      // target points staged in smem per iteration
#define SPLIT 32       // blocks splitting the M loop (chunk = M_/SPLIT == TILE)

// Scratch (allocation-free: __device__ globals)
__device__ unsigned int g_minPT[B_ * N_];   // min over m of d(pred_n, target_m)
__device__ unsigned int g_minTP[B_ * M_];   // min over n of d(target_m, pred_n)
__device__ unsigned int g_minPP[B_ * N_];   // min over m!=n of d(pred_n, pred_m)
__device__ double       g_partial[B_ * 4];  // per-b: sumPT, sumTP, sumPP, sumPP2

__global__ void init_kernel() {
    int i = blockIdx.x * blockDim.x + threadIdx.x;
    if (i < B_ * N_) {
        g_minPT[i] = 0x7f800000u;  // +inf
        g_minTP[i] = 0x7f800000u;
        g_minPP[i] = 0x7f800000u;
    }
}

// W = 0: pred->target into g_minPT
// W = 1: target->pred into g_minTP
// W = 2: pred->pred (self-masked) into g_minPP
template <int W>
__global__ void pairmin_kernel(const float* __restrict__ A,
                               const float* __restrict__ P) {
    __shared__ float sx[TILE], sy[TILE], sz[TILE];

    unsigned int* out = (W == 0) ? g_minPT : (W == 1) ? g_minTP : g_minPP;

    const int b = blockIdx.y;
    const int t = threadIdx.x;
    const int qbase = blockIdx.x * (TPB * KQ);

    float px[KQ], py[KQ], pz[KQ], mn[KQ];
    int qi[KQ];
#pragma unroll
    for (int k = 0; k < KQ; k++) {
        qi[k] = qbase + k * TPB + t;
        const float* a = A + (size_t)(b * N_ + qi[k]) * 3;
        px[k] = a[0]; py[k] = a[1]; pz[k] = a[2];
        mn[k] = 3.4e38f;
    }

    const int chunk  = M_ / SPLIT;          // == TILE
    const int mstart = blockIdx.z * chunk;

    for (int m0 = mstart; m0 < mstart + chunk; m0 += TILE) {
        __syncthreads();
        for (int j = t; j < TILE; j += TPB) {
            const float* p = P + (size_t)(b * M_ + m0 + j) * 3;
            sx[j] = p[0]; sy[j] = p[1]; sz[j] = p[2];
        }
        __syncthreads();

#pragma unroll 4
        for (int j = 0; j < TILE; j++) {
            const float bx = sx[j], by = sy[j], bz = sz[j];
#pragma unroll
            for (int k = 0; k < KQ; k++) {
                float dx = px[k] - bx;
                float dy = py[k] - by;
                float dz = pz[k] - bz;
                float d  = fmaf(dx, dx, fmaf(dy, dy, dz * dz));
                if (W == 2) {
                    if (m0 + j != qi[k]) mn[k] = fminf(mn[k], d);
                } else {
                    mn[k] = fminf(mn[k], d);
                }
            }
        }
    }

#pragma unroll
    for (int k = 0; k < KQ; k++)
        atomicMin(&out[b * N_ + qi[k]], __float_as_uint(mn[k]));
}

// One block per batch element: double-precision sums of the three min arrays.
__global__ void reduce_kernel() {
    __shared__ double s0[256], s1[256], s2[256], s3[256];
    const int b = blockIdx.x;
    const int t = threadIdx.x;

    double a = 0.0, c = 0.0, p = 0.0, p2 = 0.0;
    for (int i = t; i < N_; i += 256) {
        a += (double)__uint_as_float(g_minPT[b * N_ + i]);
        c += (double)__uint_as_float(g_minTP[b * N_ + i]);
        double v = (double)__uint_as_float(g_minPP[b * N_ + i]);
        p  += v;
        p2 += v * v;
    }
    s0[t] = a; s1[t] = c; s2[t] = p; s3[t] = p2;
    __syncthreads();
    for (int s = 128; s > 0; s >>= 1) {
        if (t < s) {
            s0[t] += s0[t + s]; s1[t] += s1[t + s];
            s2[t] += s2[t + s]; s3[t] += s3[t + s];
        }
        __syncthreads();
    }
    if (t == 0) {
        g_partial[b * 4 + 0] = s0[0];
        g_partial[b * 4 + 1] = s1[0];
        g_partial[b * 4 + 2] = s2[0];
        g_partial[b * 4 + 3] = s3[0];
    }
}

// Single block: KL reduction + final combination.
__global__ void final_kernel(const float* __restrict__ mu,
                             const float* __restrict__ logvar,
                             float* __restrict__ out, int out_size) {
    __shared__ double sk[256];
    const int t = threadIdx.x;

    double kls = 0.0;
    for (int i = t; i < B_ * L_; i += 256) {
        float m  = mu[i];
        float lv = logvar[i];
        kls += (double)(1.0f + lv - m * m - expf(lv));
    }
    sk[t] = kls;
    __syncthreads();
    for (int s = 128; s > 0; s >>= 1) {
        if (t < s) sk[t] += sk[t + s];
        __syncthreads();
    }

    if (t == 0) {
        double kl = -0.5 * sk[0] / (double)(B_ * L_);

        double cd = 0.0, dens = 0.0;
        for (int b = 0; b < B_; b++) {
            cd += g_partial[b * 4 + 0] / (double)N_
                + g_partial[b * 4 + 1] / (double)M_;
            double s  = g_partial[b * 4 + 2];
            double s2 = g_partial[b * 4 + 3];
            double var = (s2 - s * s / (double)N_) / (double)(N_ - 1);
            dens += sqrt(var > 0.0 ? var : 0.0);
        }
        cd   /= (double)B_;
        dens /= (double)B_;

        double total = cd + 0.001 * kl + 0.1 * dens;

        if (out_size > 0) out[0] = (float)total;
        if (out_size > 1) out[1] = (float)cd;
        if (out_size > 2) out[2] = (float)kl;
        if (out_size > 3) out[3] = (float)dens;
    }
}

extern "C" void kernel_launch(void* const* d_in, const int* in_sizes, int n_in,
                              void* d_out, int out_size) {
    const float* pred   = (const float*)d_in[0];
    const float* target = (const float*)d_in[1];
    const float* mu     = (const float*)d_in[2];
    const float* logvar = (const float*)d_in[3];
    float* out = (float*)d_out;

    init_kernel<<<(B_ * N_ + 255) / 256, 256>>>();

    dim3 grid(N_ / (TPB * KQ), B_, SPLIT);  // (8, 2, 32) = 512 blocks
    pairmin_kernel<0><<<grid, TPB>>>(pred,   target);
    pairmin_kernel<1><<<grid, TPB>>>(target, pred);
    pairmin_kernel<2><<<grid, TPB>>>(pred,   pred);

    reduce_kernel<<<B_, 256>>>();
    final_kernel<<<1, 256>>>(mu, logvar, out, out_size);
}

// round 2
// speedup vs baseline: 1.1812x; 1.1812x over previous
#include <cuda_runtime.h>
#include <cuda_bf16.h>
#include <math.h>

// Problem shape (fixed by reference setup_inputs)
#define B_    2
#define N_    4096
#define M_    4096
#define L_    512
#define TPB   128      // threads per block in pairmin
#define KQ    4        // queries per thread (register blocking)
#define TILE  128      // target points per block tile (== M_/SPLIT)
#define SPLIT 32

// Scratch (allocation-free: __device__ globals)
// g_min[pass][b][n]: pass 0 = pred->target, 1 = target->pred, 2 = pred->pred
__device__ unsigned int g_min[3][B_][N_];

__global__ void init_kernel() {
    int i = blockIdx.x * blockDim.x + threadIdx.x;
    if (i < 3 * B_ * N_) ((unsigned int*)g_min)[i] = 0x7f800000u;  // +inf
}

// One launch covers all 3 passes: blockIdx.z in [0,96), pass = z>>5, split = z&31.
// Inner loop uses d = |p|^2 + (|t|^2 - 2 p.t): tile holds (-2x,-2y,-2z,|t|^2)
// as float4 -> 3 FFMA + 1 FMNMX per pair, one broadcast LDS.128 per tile elem.
__global__ void __launch_bounds__(TPB) pairmin_all(const float* __restrict__ pred,
                                                   const float* __restrict__ target) {
    __shared__ float4 s[TILE];

    const int z     = blockIdx.z;
    const int pass  = z >> 5;          // 0,1,2
    const int split = z & 31;
    const int b     = blockIdx.y;
    const int t     = threadIdx.x;

    const float* A = (pass == 1) ? target : pred;   // query set
    const float* P = (pass == 0) ? target : pred;   // tile set

    const int qbase = blockIdx.x * (TPB * KQ);

    float px[KQ], py[KQ], pz[KQ], pp[KQ], mn[KQ];
    int qi[KQ];
#pragma unroll
    for (int k = 0; k < KQ; k++) {
        qi[k] = qbase + k * TPB + t;
        const float* a = A + (size_t)(b * N_ + qi[k]) * 3;
        px[k] = a[0]; py[k] = a[1]; pz[k] = a[2];
        pp[k] = fmaf(px[k], px[k], fmaf(py[k], py[k], pz[k] * pz[k]));
        mn[k] = 3.4e38f;
    }

    // Stage this block's tile (TILE == TPB: one point per thread)
    const int m0 = split * TILE;
    {
        const float* p = P + (size_t)(b * M_ + m0 + t) * 3;
        float x = p[0], y = p[1], zz = p[2];
        s[t] = make_float4(-2.f * x, -2.f * y, -2.f * zz,
                           fmaf(x, x, fmaf(y, y, zz * zz)));
    }
    __syncthreads();

    if (pass == 2) {
        // self-masked pred->pred
#pragma unroll 8
        for (int j = 0; j < TILE; j++) {
            const float4 v = s[j];
            const int m = m0 + j;
#pragma unroll
            for (int k = 0; k < KQ; k++) {
                float e = fmaf(px[k], v.x, fmaf(py[k], v.y, fmaf(pz[k], v.z, v.w)));
                if (m != qi[k]) mn[k] = fminf(mn[k], e);
            }
        }
    } else {
#pragma unroll 8
        for (int j = 0; j < TILE; j++) {
            const float4 v = s[j];
#pragma unroll
            for (int k = 0; k < KQ; k++) {
                float e = fmaf(px[k], v.x, fmaf(py[k], v.y, fmaf(pz[k], v.z, v.w)));
                mn[k] = fminf(mn[k], e);
            }
        }
    }

#pragma unroll
    for (int k = 0; k < KQ; k++) {
        float d = fmaxf(pp[k] + mn[k], 0.0f);   // clamp: uint ordering needs d >= 0
        atomicMin(&g_min[pass][b][qi[k]], __float_as_uint(d));
    }
}

// Single block: all reductions (chamfer sums, per-b PP sums for std, KL) + final.
__global__ void finalize_kernel(const float* __restrict__ mu,
                                const float* __restrict__ logvar,
                                float* __restrict__ out, int out_size) {
    __shared__ double sm[6][256];
    const int t = threadIdx.x;

    double acc[6] = {0, 0, 0, 0, 0, 0};
    // acc0: sum(PT)+sum(TP) over all b ; acc1/2: sumPP, sumPP2 for b=0
    // acc3/4: sumPP, sumPP2 for b=1   ; acc5: KL sum
    for (int i = t; i < B_ * N_; i += 256) {
        acc[0] += (double)__uint_as_float(((unsigned int*)g_min[0])[i]);
        acc[0] += (double)__uint_as_float(((unsigned int*)g_min[1])[i]);
    }
    for (int b = 0; b < B_; b++) {
        for (int i = t; i < N_; i += 256) {
            double v = (double)__uint_as_float(g_min[2][b][i]);
            acc[1 + 2 * b] += v;
            acc[2 + 2 * b] += v * v;
        }
    }
    for (int i = t; i < B_ * L_; i += 256) {
        float m  = mu[i];
        float lv = logvar[i];
        acc[5] += (double)(1.0f + lv - m * m - expf(lv));
    }

#pragma unroll
    for (int r = 0; r < 6; r++) sm[r][t] = acc[r];
    __syncthreads();
    for (int s = 128; s > 0; s >>= 1) {
        if (t < s) {
#pragma unroll
            for (int r = 0; r < 6; r++) sm[r][t] += sm[r][t + s];
        }
        __syncthreads();
    }

    if (t == 0) {
        double cd = sm[0][0] / (double)(B_ * N_);  // mean over b of (meanPT + meanTP)
        double dens = 0.0;
        for (int b = 0; b < B_; b++) {
            double s  = sm[1 + 2 * b][0];
            double s2 = sm[2 + 2 * b][0];
            double var = (s2 - s * s / (double)N_) / (double)(N_ - 1);
            dens += sqrt(var > 0.0 ? var : 0.0);
        }
        dens /= (double)B_;
        double kl = -0.5 * sm[5][0] / (double)(B_ * L_);
        double total = cd + 0.001 * kl + 0.1 * dens;

        if (out_size > 0) out[0] = (float)total;
        if (out_size > 1) out[1] = (float)cd;
        if (out_size > 2) out[2] = (float)kl;
        if (out_size > 3) out[3] = (float)dens;
    }
}

extern "C" void kernel_launch(void* const* d_in, const int* in_sizes, int n_in,
                              void* d_out, int out_size) {
    const float* pred   = (const float*)d_in[0];
    const float* target = (const float*)d_in[1];
    const float* mu     = (const float*)d_in[2];
    const float* logvar = (const float*)d_in[3];
    float* out = (float*)d_out;

    init_kernel<<<(3 * B_ * N_ + 255) / 256, 256>>>();

    dim3 grid(N_ / (TPB * KQ), B_, 3 * SPLIT);   // (8, 2, 96) = 1536 blocks
    pairmin_all<<<grid, TPB>>>(pred, target);

    finalize_kernel<<<1, 256>>>(mu, logvar, out, out_size);
}

// round 3
// speedup vs baseline: 1.5236x; 1.2899x over previous
#include <cuda_runtime.h>
#include <cuda_bf16.h>
#include <math.h>

// Problem shape (fixed by reference setup_inputs)
#define B_    2
#define N_    4096
#define M_    4096
#define L_    512
#define TPB   128          // threads per pairmin block
#define KQ    8            // queries per thread
#define KP    (KQ/2)       // packed query pairs
#define TILE  64           // tile points per block
#define SPLIT 64           // M_/TILE
#define QBLK  (TPB*KQ)     // 1024 queries per block (x-dim)
#define NQB   (N_/QBLK)    // 4
#define RBLKS (3*B_*(N_/256))  // 96 reduce blocks

// Scratch (allocation-free: __device__ globals)
__device__ float        g_part[3 * B_ * SPLIT * N_];  // 6 MB partial mins
__device__ double       g_acc[6];                     // sums (zero-init, self-resetting)
__device__ unsigned int g_count;                      // completion counter

// ---- f32x2 packed helpers -------------------------------------------------
static __device__ __forceinline__ unsigned long long pk2(float lo, float hi) {
    unsigned long long r;
    asm("mov.b64 %0, {%1,%2};" : "=l"(r) : "f"(lo), "f"(hi));
    return r;
}
static __device__ __forceinline__ unsigned long long fma2(
        unsigned long long a, unsigned long long b, unsigned long long c) {
    unsigned long long d;
    asm("fma.rn.f32x2 %0, %1, %2, %3;" : "=l"(d) : "l"(a), "l"(b), "l"(c));
    return d;
}
static __device__ __forceinline__ void upk2(unsigned long long v, float& lo, float& hi) {
    asm("mov.b64 {%0,%1}, %2;" : "=f"(lo), "=f"(hi) : "l"(v));
}

// ---- pass blocks: z in [0, 3*SPLIT); pass = z/SPLIT, split = z%SPLIT -------
// d(p,t) = |p|^2 + (|t|^2 - 2 p.t); tile holds pair-duplicated
// (-2x,-2x),(-2y,-2y),(-2z,-2z),(ss,ss) -> 3 FFMA2 per 2 pairs.
__global__ void __launch_bounds__(TPB) pairmin_all(const float* __restrict__ pred,
                                                   const float* __restrict__ target) {
    __shared__ unsigned long long sd[TILE][4];

    const int z     = blockIdx.z;
    const int pass  = z / SPLIT;
    const int split = z % SPLIT;
    const int b     = blockIdx.y;
    const int t     = threadIdx.x;

    const float* A = (pass == 1) ? target : pred;   // query set
    const float* P = (pass == 0) ? target : pred;   // tile set

    const int qbase = blockIdx.x * QBLK;
    const int m0    = split * TILE;

    // stage tile (TILE=64 < TPB: first 64 threads)
    if (t < TILE) {
        const float* p = P + (size_t)(b * M_ + m0 + t) * 3;
        float x = p[0], y = p[1], zz = p[2];
        float ss = fmaf(x, x, fmaf(y, y, zz * zz));
        sd[t][0] = pk2(-2.f * x,  -2.f * x);
        sd[t][1] = pk2(-2.f * y,  -2.f * y);
        sd[t][2] = pk2(-2.f * zz, -2.f * zz);
        sd[t][3] = pk2(ss, ss);
    }

    unsigned long long px2[KP], py2[KP], pz2[KP];
    float pp[KQ], mn[KQ];
#pragma unroll
    for (int kp = 0; kp < KP; kp++) {
        const int q0 = qbase + (2 * kp)     * TPB + t;
        const int q1 = qbase + (2 * kp + 1) * TPB + t;
        const float* a0 = A + (size_t)(b * N_ + q0) * 3;
        const float* a1 = A + (size_t)(b * N_ + q1) * 3;
        float x0 = a0[0], y0 = a0[1], z0 = a0[2];
        float x1 = a1[0], y1 = a1[1], z1 = a1[2];
        px2[kp] = pk2(x0, x1); py2[kp] = pk2(y0, y1); pz2[kp] = pk2(z0, z1);
        pp[2 * kp]     = fmaf(x0, x0, fmaf(y0, y0, z0 * z0));
        pp[2 * kp + 1] = fmaf(x1, x1, fmaf(y1, y1, z1 * z1));
        mn[2 * kp]     = 3.4e38f;
        mn[2 * kp + 1] = 3.4e38f;
    }
    __syncthreads();

    const bool diag = (pass == 2) && (m0 >= qbase) && (m0 < qbase + QBLK);
    if (!diag) {
        // fast branch-free loop (92% of blocks)
#pragma unroll 8
        for (int j = 0; j < TILE; j++) {
            const ulonglong2 v01 = *reinterpret_cast<const ulonglong2*>(&sd[j][0]);
            const ulonglong2 v23 = *reinterpret_cast<const ulonglong2*>(&sd[j][2]);
#pragma unroll
            for (int kp = 0; kp < KP; kp++) {
                unsigned long long e = fma2(pz2[kp], v23.x, v23.y);
                e = fma2(py2[kp], v01.y, e);
                e = fma2(px2[kp], v01.x, e);
                float lo, hi; upk2(e, lo, hi);
                mn[2 * kp]     = fminf(mn[2 * kp],     lo);
                mn[2 * kp + 1] = fminf(mn[2 * kp + 1], hi);
            }
        }
    } else {
        // self-masked loop for diagonal pred->pred blocks
#pragma unroll 4
        for (int j = 0; j < TILE; j++) {
            const ulonglong2 v01 = *reinterpret_cast<const ulonglong2*>(&sd[j][0]);
            const ulonglong2 v23 = *reinterpret_cast<const ulonglong2*>(&sd[j][2]);
            const int m = m0 + j;
#pragma unroll
            for (int kp = 0; kp < KP; kp++) {
                unsigned long long e = fma2(pz2[kp], v23.x, v23.y);
                e = fma2(py2[kp], v01.y, e);
                e = fma2(px2[kp], v01.x, e);
                float lo, hi; upk2(e, lo, hi);
                if (m != qbase + (2 * kp)     * TPB + t)
                    mn[2 * kp]     = fminf(mn[2 * kp],     lo);
                if (m != qbase + (2 * kp + 1) * TPB + t)
                    mn[2 * kp + 1] = fminf(mn[2 * kp + 1], hi);
            }
        }
    }

    // plain stores: every slot written exactly once -> no init, no atomics
    float* dst = g_part + ((size_t)((pass * B_ + b) * SPLIT + split)) * N_ + qbase + t;
#pragma unroll
    for (int k = 0; k < KQ; k++)
        dst[k * TPB] = pp[k] + mn[k];
}

// ---- fused reduce + finalize (fence+counter last-block pattern) -----------
__global__ void __launch_bounds__(256) reduce_final(const float* __restrict__ mu,
                                                    const float* __restrict__ logvar,
                                                    float* __restrict__ out,
                                                    int out_size) {
    __shared__ double s1s[256], s2s[256], sks[256];
    __shared__ bool last;

    const int t    = threadIdx.x;
    const int blk  = blockIdx.x;          // 0..95
    const int pb   = blk >> 4;            // 16 blocks per (pass,b)
    const int pass = pb >> 1;
    const int b    = pb & 1;
    const int q    = (blk & 15) * 256 + t;

    const float* base = g_part + ((size_t)((pass * B_ + b) * SPLIT)) * N_ + q;
    float v = base[0];
#pragma unroll
    for (int s = 1; s < SPLIT; s++) v = fminf(v, base[(size_t)s * N_]);

    double s1 = (double)v;
    double s2 = (double)v * (double)v;

    double kls = 0.0;
    if (blk == 0) {
        for (int i = t; i < B_ * L_; i += 256) {
            double m  = (double)mu[i];
            double lv = (double)logvar[i];
            kls += 1.0 + lv - m * m - exp(lv);
        }
    }

    s1s[t] = s1; s2s[t] = s2; sks[t] = kls;
    __syncthreads();
    for (int s = 128; s > 0; s >>= 1) {
        if (t < s) {
            s1s[t] += s1s[t + s];
            s2s[t] += s2s[t + s];
            sks[t] += sks[t + s];
        }
        __syncthreads();
    }

    if (t == 0) {
        if (pass < 2) {
            atomicAdd(&g_acc[0], s1s[0]);            // PT + TP combined
        } else {
            atomicAdd(&g_acc[1 + 2 * b], s1s[0]);    // PP sum
            atomicAdd(&g_acc[2 + 2 * b], s2s[0]);    // PP sum of squares
        }
        if (blk == 0) atomicAdd(&g_acc[5], sks[0]);  // KL sum
        __threadfence();
        unsigned int n = atomicAdd(&g_count, 1u);
        last = (n == RBLKS - 1);
    }
    __syncthreads();

    if (last && t == 0) {
        __threadfence();
        volatile double* acc = g_acc;
        double cd = acc[0] / (double)(B_ * N_);
        double dens = 0.0;
        for (int bb = 0; bb < B_; bb++) {
            double su  = acc[1 + 2 * bb];
            double su2 = acc[2 + 2 * bb];
            double var = (su2 - su * su / (double)N_) / (double)(N_ - 1);
            dens += sqrt(var > 0.0 ? var : 0.0);
        }
        dens /= (double)B_;
        double kl = -0.5 * acc[5] / (double)(B_ * L_);
        double total = cd + 0.001 * kl + 0.1 * dens;

        if (out_size > 0) out[0] = (float)total;
        if (out_size > 1) out[1] = (float)cd;
        if (out_size > 2) out[2] = (float)kl;
        if (out_size > 3) out[3] = (float)dens;

        // reset for next graph replay
        for (int i = 0; i < 6; i++) g_acc[i] = 0.0;
        __threadfence();
        g_count = 0u;
    }
}

extern "C" void kernel_launch(void* const* d_in, const int* in_sizes, int n_in,
                              void* d_out, int out_size) {
    const float* pred   = (const float*)d_in[0];
    const float* target = (const float*)d_in[1];
    const float* mu     = (const float*)d_in[2];
    const float* logvar = (const float*)d_in[3];
    float* out = (float*)d_out;

    dim3 grid(NQB, B_, 3 * SPLIT);   // (4, 2, 192) = 1536 blocks
    pairmin_all<<<grid, TPB>>>(pred, target);

    reduce_final<<<RBLKS, 256>>>(mu, logvar, out, out_size);
}

// round 4
// speedup vs baseline: 1.5263x; 1.0018x over previous
#include <cuda_runtime.h>
#include <cuda_bf16.h>
#include <math.h>

// Problem shape (fixed by reference setup_inputs)
#define B_    2
#define N_    4096
#define M_    4096
#define L_    512
#define TPB   128          // threads per pairmin block
#define KQ    8            // queries per thread
#define KP    (KQ/2)       // packed query pairs
#define TILE  64           // tile points per block
#define SPLIT 64           // M_/TILE
#define QBLK  (TPB*KQ)     // 1024 queries per block (x-dim)
#define NQB   (N_/QBLK)    // 4
#define RBLKS (3*B_*(N_/64))   // 384 reduce blocks

// Scratch (allocation-free: __device__ globals)
__device__ float        g_part[3 * B_ * SPLIT * N_];  // 6 MB partial mins
__device__ double       g_acc[6];                     // sums (zero-init, self-resetting)
__device__ unsigned int g_count;                      // completion counter

// ---- f32x2 packed helpers -------------------------------------------------
static __device__ __forceinline__ unsigned long long pk2(float lo, float hi) {
    unsigned long long r;
    asm("mov.b64 %0, {%1,%2};" : "=l"(r) : "f"(lo), "f"(hi));
    return r;
}
static __device__ __forceinline__ unsigned long long fma2(
        unsigned long long a, unsigned long long b, unsigned long long c) {
    unsigned long long d;
    asm("fma.rn.f32x2 %0, %1, %2, %3;" : "=l"(d) : "l"(a), "l"(b), "l"(c));
    return d;
}
static __device__ __forceinline__ void upk2(unsigned long long v, float& lo, float& hi) {
    asm("mov.b64 {%0,%1}, %2;" : "=f"(lo), "=f"(hi) : "l"(v));
}

// ---- pass blocks: z in [0, 3*SPLIT); pass = z/SPLIT, split = z%SPLIT -------
// d(p,t) = |p|^2 + (|t|^2 - 2 p.t); tile holds pair-duplicated
// (-2x,-2x),(-2y,-2y),(-2z,-2z),(ss,ss) -> 3 FFMA2 per 2 pairs.
__global__ void __launch_bounds__(TPB) pairmin_all(const float* __restrict__ pred,
                                                   const float* __restrict__ target) {
    __shared__ unsigned long long sd[TILE][4];

    const int z     = blockIdx.z;
    const int pass  = z / SPLIT;
    const int split = z % SPLIT;
    const int b     = blockIdx.y;
    const int t     = threadIdx.x;

    const float* A = (pass == 1) ? target : pred;   // query set
    const float* P = (pass == 0) ? target : pred;   // tile set

    const int qbase = blockIdx.x * QBLK;
    const int m0    = split * TILE;

    // stage tile (TILE=64 < TPB: first 64 threads)
    if (t < TILE) {
        const float* p = P + (size_t)(b * M_ + m0 + t) * 3;
        float x = p[0], y = p[1], zz = p[2];
        float ss = fmaf(x, x, fmaf(y, y, zz * zz));
        sd[t][0] = pk2(-2.f * x,  -2.f * x);
        sd[t][1] = pk2(-2.f * y,  -2.f * y);
        sd[t][2] = pk2(-2.f * zz, -2.f * zz);
        sd[t][3] = pk2(ss, ss);
    }

    unsigned long long px2[KP], py2[KP], pz2[KP];
    float pp[KQ], mn[KQ];
#pragma unroll
    for (int kp = 0; kp < KP; kp++) {
        const int q0 = qbase + (2 * kp)     * TPB + t;
        const int q1 = qbase + (2 * kp + 1) * TPB + t;
        const float* a0 = A + (size_t)(b * N_ + q0) * 3;
        const float* a1 = A + (size_t)(b * N_ + q1) * 3;
        float x0 = a0[0], y0 = a0[1], z0 = a0[2];
        float x1 = a1[0], y1 = a1[1], z1 = a1[2];
        px2[kp] = pk2(x0, x1); py2[kp] = pk2(y0, y1); pz2[kp] = pk2(z0, z1);
        pp[2 * kp]     = fmaf(x0, x0, fmaf(y0, y0, z0 * z0));
        pp[2 * kp + 1] = fmaf(x1, x1, fmaf(y1, y1, z1 * z1));
        mn[2 * kp]     = 3.4e38f;
        mn[2 * kp + 1] = 3.4e38f;
    }
    __syncthreads();

    const bool diag = (pass == 2) && (m0 >= qbase) && (m0 < qbase + QBLK);
    if (!diag) {
        // fast branch-free loop (~97% of blocks)
#pragma unroll 8
        for (int j = 0; j < TILE; j++) {
            const ulonglong2 v01 = *reinterpret_cast<const ulonglong2*>(&sd[j][0]);
            const ulonglong2 v23 = *reinterpret_cast<const ulonglong2*>(&sd[j][2]);
#pragma unroll
            for (int kp = 0; kp < KP; kp++) {
                unsigned long long e = fma2(pz2[kp], v23.x, v23.y);
                e = fma2(py2[kp], v01.y, e);
                e = fma2(px2[kp], v01.x, e);
                float lo, hi; upk2(e, lo, hi);
                mn[2 * kp]     = fminf(mn[2 * kp],     lo);
                mn[2 * kp + 1] = fminf(mn[2 * kp + 1], hi);
            }
        }
    } else {
        // self-masked loop for diagonal pred->pred blocks
#pragma unroll 4
        for (int j = 0; j < TILE; j++) {
            const ulonglong2 v01 = *reinterpret_cast<const ulonglong2*>(&sd[j][0]);
            const ulonglong2 v23 = *reinterpret_cast<const ulonglong2*>(&sd[j][2]);
            const int m = m0 + j;
#pragma unroll
            for (int kp = 0; kp < KP; kp++) {
                unsigned long long e = fma2(pz2[kp], v23.x, v23.y);
                e = fma2(py2[kp], v01.y, e);
                e = fma2(px2[kp], v01.x, e);
                float lo, hi; upk2(e, lo, hi);
                if (m != qbase + (2 * kp)     * TPB + t)
                    mn[2 * kp]     = fminf(mn[2 * kp],     lo);
                if (m != qbase + (2 * kp + 1) * TPB + t)
                    mn[2 * kp + 1] = fminf(mn[2 * kp + 1], hi);
            }
        }
    }

    // plain stores: every slot written exactly once -> no init, no atomics
    float* dst = g_part + ((size_t)((pass * B_ + b) * SPLIT + split)) * N_ + qbase + t;
#pragma unroll
    for (int k = 0; k < KQ; k++)
        dst[k * TPB] = pp[k] + mn[k];
}

// ---- fused reduce + finalize ------------------------------------------------
// 384 blocks: block = (pass, b, qchunk of 64 queries).
// Thread layout: q = t&63 (coalesced), split-group sg = t>>6 handles 16 splits.
__global__ void __launch_bounds__(256) reduce_final(const float* __restrict__ mu,
                                                    const float* __restrict__ logvar,
                                                    float* __restrict__ out,
                                                    int out_size) {
    __shared__ float  smin[256];
    __shared__ double s1s[2], s2s[2], sks[8];
    __shared__ bool   last;

    const int t    = threadIdx.x;
    const int blk  = blockIdx.x;          // 0..383
    const int pb   = blk >> 6;            // (pass*B + b): 0..5
    const int pass = pb >> 1;
    const int b    = pb & 1;
    const int q    = (blk & 63) * 64 + (t & 63);
    const int sg   = t >> 6;              // 0..3 -> splits [16*sg, 16*sg+16)

    // strided min over 16 splits (independent loads, coalesced across q)
    const float* base = g_part + ((size_t)(pb * SPLIT + sg * 16)) * N_ + q;
    float v = base[0];
#pragma unroll
    for (int s = 1; s < 16; s++) v = fminf(v, base[(size_t)s * N_]);
    smin[t] = v;

    // KL in block 0 (overlapped with the min combine)
    double kls = 0.0;
    if (blk == 0) {
        for (int i = t; i < B_ * L_; i += 256) {
            double m  = (double)mu[i];
            double lv = (double)logvar[i];
            kls += 1.0 + lv - m * m - exp(lv);
        }
#pragma unroll
        for (int o = 16; o > 0; o >>= 1)
            kls += __shfl_down_sync(0xffffffffu, kls, o);
        if ((t & 31) == 0) sks[t >> 5] = kls;
    }
    __syncthreads();

    if (t < 128) smin[t] = fminf(smin[t], smin[t + 128]);
    __syncthreads();

    if (t < 64) {
        float nn = fminf(smin[t], smin[t + 64]);   // final nn_dist for query q
        double d1 = (double)nn;
        double d2 = d1 * d1;
#pragma unroll
        for (int o = 16; o > 0; o >>= 1) {
            d1 += __shfl_down_sync(0xffffffffu, d1, o);
            d2 += __shfl_down_sync(0xffffffffu, d2, o);
        }
        if ((t & 31) == 0) { s1s[t >> 5] = d1; s2s[t >> 5] = d2; }
    }
    __syncthreads();

    if (t == 0) {
        double s1 = s1s[0] + s1s[1];
        if (pass < 2) {
            atomicAdd(&g_acc[0], s1);                        // PT + TP combined
        } else {
            atomicAdd(&g_acc[1 + 2 * b], s1);                // PP sum
            atomicAdd(&g_acc[2 + 2 * b], s2s[0] + s2s[1]);   // PP sum of squares
        }
        if (blk == 0) {
            double k = 0.0;
#pragma unroll
            for (int w = 0; w < 8; w++) k += sks[w];
            atomicAdd(&g_acc[5], k);
        }
        __threadfence();
        unsigned int n = atomicAdd(&g_count, 1u);
        last = (n == RBLKS - 1);
    }
    __syncthreads();

    if (last && t == 0) {
        __threadfence();
        volatile double* acc = g_acc;
        double cd = acc[0] / (double)(B_ * N_);
        double dens = 0.0;
        for (int bb = 0; bb < B_; bb++) {
            double su  = acc[1 + 2 * bb];
            double su2 = acc[2 + 2 * bb];
            double var = (su2 - su * su / (double)N_) / (double)(N_ - 1);
            dens += sqrt(var > 0.0 ? var : 0.0);
        }
        dens /= (double)B_;
        double kl = -0.5 * acc[5] / (double)(B_ * L_);
        double total = cd + 0.001 * kl + 0.1 * dens;

        if (out_size > 0) out[0] = (float)total;
        if (out_size > 1) out[1] = (float)cd;
        if (out_size > 2) out[2] = (float)kl;
        if (out_size > 3) out[3] = (float)dens;

        // reset for next graph replay
        for (int i = 0; i < 6; i++) g_acc[i] = 0.0;
        __threadfence();
        g_count = 0u;
    }
}

extern "C" void kernel_launch(void* const* d_in, const int* in_sizes, int n_in,
                              void* d_out, int out_size) {
    const float* pred   = (const float*)d_in[0];
    const float* target = (const float*)d_in[1];
    const float* mu     = (const float*)d_in[2];
    const float* logvar = (const float*)d_in[3];
    float* out = (float*)d_out;

    dim3 grid(NQB, B_, 3 * SPLIT);   // (4, 2, 192) = 1536 blocks
    pairmin_all<<<grid, TPB>>>(pred, target);

    reduce_final<<<RBLKS, 256>>>(mu, logvar, out, out_size);
}